// round 11
// baseline (speedup 1.0000x reference)
#include <cuda_runtime.h>
#include <cuda_fp16.h>
#include <cstdint>
#include <cstddef>

// ---------------------------------------------------------------------------
// out = (relu(x @ qdq(w_fc)^T)^2) @ qdq(w_proj)^T
// M=8192, K1=2048, N1=8192 ; K2=8192, N2=2048
// Round 11: verified R7/R10 GEMM mainloop. New:
//  - GEMM2 split-K=2 (gridDim.z): 1024->2048 CTAs kills the 4-wave/46%-tail
//    quantization (~13% idle). Partials to g_part, float4 reduce -> out.
//  - generalized pipeline tail for (KT-2)%3 == 2 (KT=64 per split).
//  - prep (quant wfc, quant wproj, x->fp16) fused into ONE kernel launch.
// ---------------------------------------------------------------------------

#define BM 128
#define BN 128
#define BKH 64                    // halves per k-tile (128 B rows)
#define STAGE_A (BM * 128)        // bytes
#define STAGE_B (BN * 128)
#define STAGE_BYTES (STAGE_A + STAGE_B)          // 32768
#define SMEM_TOTAL (3 * STAGE_BYTES)             // 98304

// Scratch (allocation-free)
__device__ __align__(256) __half g_xh[8192ull * 2048];
__device__ __align__(256) __half g_wfc[8192ull * 2048];
__device__ __align__(256) __half g_wpj[2048ull * 8192];
__device__ __align__(256) __half g_h2[8192ull * 8192];
__device__ __align__(256) float  g_part[2ull * 8192 * 2048];   // split-K partials

// ---------------------------------------------------------------------------
__device__ __forceinline__ void cp16(uint32_t s, const void* g) {
    asm volatile("cp.async.cg.shared.global [%0], [%1], 16;" :: "r"(s), "l"(g));
}
__device__ __forceinline__ void cp_commit() { asm volatile("cp.async.commit_group;"); }
template <int N>
__device__ __forceinline__ void cp_wait() { asm volatile("cp.async.wait_group %0;" :: "n"(N)); }

__device__ __forceinline__ void ldsm4(uint32_t& r0, uint32_t& r1, uint32_t& r2,
                                      uint32_t& r3, uint32_t addr) {
    asm volatile("ldmatrix.sync.aligned.m8n8.x4.shared.b16 {%0,%1,%2,%3}, [%4];"
                 : "=r"(r0), "=r"(r1), "=r"(r2), "=r"(r3) : "r"(addr));
}

__device__ __forceinline__ void mma16(float c[4], const uint32_t a[4], const uint32_t b[2]) {
    asm volatile(
        "mma.sync.aligned.m16n8k16.row.col.f32.f16.f16.f32 "
        "{%0,%1,%2,%3}, {%4,%5,%6,%7}, {%8,%9}, {%0,%1,%2,%3};"
        : "+f"(c[0]), "+f"(c[1]), "+f"(c[2]), "+f"(c[3])
        : "r"(a[0]), "r"(a[1]), "r"(a[2]), "r"(a[3]), "r"(b[0]), "r"(b[1]));
}

// ---------------------------------------------------------------------------
// Quant body (verified R10 bit-exact): warp per 64-block, ILP butterfly.
// ---------------------------------------------------------------------------
__device__ __forceinline__ void quant_block(const float* __restrict__ w,
                                            __half* __restrict__ wq,
                                            int b, int lane) {
    const float* p = w + (size_t)b * 64;
    float w0 = p[lane];
    float w1 = p[lane + 32];

    float amax = fmaxf(fabsf(w0), fabsf(w1));
    #pragma unroll
    for (int o = 16; o; o >>= 1) amax = fmaxf(amax, __shfl_xor_sync(0xffffffffu, amax, o));

    float am = fmaxf(amax, 1e-8f);
    float base = __fdiv_rn(am, 15.0f);
    float invb = __fdiv_rn(15.0f, am);

    const float shr[16] = {0.4f, 0.44f, 0.48f, 0.52f, 0.56f, 0.6f, 0.64f, 0.68f,
                           0.72f, 0.76f, 0.8f, 0.84f, 0.88f, 0.92f, 0.96f, 1.0f};
    const float ishr[16] = {2.5f, 1.0f/0.44f, 1.0f/0.48f, 1.0f/0.52f,
                            1.0f/0.56f, 1.0f/0.6f, 1.0f/0.64f, 1.0f/0.68f,
                            1.0f/0.72f, 1.0f/0.76f, 1.25f, 1.0f/0.84f,
                            1.0f/0.88f, 1.0f/0.92f, 1.0f/0.96f, 1.0f};

    float e[16];
    #pragma unroll
    for (int i = 0; i < 16; i++) {
        float s = base * shr[i];
        float inv = invb * ishr[i];
        float q0 = fminf(fmaxf(rintf(w0 * inv), -15.f), 15.f);
        float q1 = fminf(fmaxf(rintf(w1 * inv), -15.f), 15.f);
        float d0 = fmaf(q0, s, -w0);
        float d1 = fmaf(q1, s, -w1);
        e[i] = fmaf(d0, d0, d1 * d1);
    }
    #pragma unroll
    for (int o = 16; o; o >>= 1) {
        #pragma unroll
        for (int i = 0; i < 16; i++)
            e[i] += __shfl_xor_sync(0xffffffffu, e[i], o);
    }
    float best_err = e[0];
    int idx = 0;
    #pragma unroll
    for (int i = 1; i < 16; i++)
        if (e[i] < best_err) { best_err = e[i]; idx = i; }

    float best_scale = base * shr[idx];
    float best_inv = invb * ishr[idx];
    float q0 = fminf(fmaxf(rintf(w0 * best_inv), -15.f), 15.f);
    float q1 = fminf(fmaxf(rintf(w1 * best_inv), -15.f), 15.f);
    wq[(size_t)b * 64 + lane]      = __float2half_rn(q0 * best_scale);
    wq[(size_t)b * 64 + lane + 32] = __float2half_rn(q1 * best_scale);
}

// Fused prep: [0,QB) quant wfc, [QB,2QB) quant wproj, [2QB,2QB+CONV) x->fp16.
#define QB_CTAS 32768            // 262144 blocks / 8 per CTA
#define CONV_CTAS 2048
__global__ __launch_bounds__(256)
void prep_kernel(const float* __restrict__ wfc, const float* __restrict__ wpj,
                 const float* __restrict__ x,
                 __half* __restrict__ wfcq, __half* __restrict__ wpjq,
                 __half* __restrict__ xh) {
    int cta = blockIdx.x;
    if (cta < 2 * QB_CTAS) {
        const float* w = (cta < QB_CTAS) ? wfc : wpj;
        __half* wq = (cta < QB_CTAS) ? wfcq : wpjq;
        int base_cta = (cta < QB_CTAS) ? cta : cta - QB_CTAS;
        int b = base_cta * 8 + (threadIdx.x >> 5);
        quant_block(w, wq, b, threadIdx.x & 31);
    } else {
        int bid = cta - 2 * QB_CTAS;
        const int n4 = (8192 * 2048) / 4;
        int i = bid * 256 + threadIdx.x;
        const int stride = CONV_CTAS * 256;
        for (; i < n4; i += stride) {
            float4 v = reinterpret_cast<const float4*>(x)[i];
            __half2 h0 = __floats2half2_rn(v.x, v.y);
            __half2 h1 = __floats2half2_rn(v.z, v.w);
            uint2 pk;
            pk.x = *reinterpret_cast<uint32_t*>(&h0);
            pk.y = *reinterpret_cast<uint32_t*>(&h1);
            reinterpret_cast<uint2*>(xh)[i] = pk;
        }
    }
}

// out = p0 + p1 (float4 grid-stride)
__global__ void reduce_kernel(const float* __restrict__ p0, const float* __restrict__ p1,
                              float* __restrict__ out, int n4) {
    int i = blockIdx.x * blockDim.x + threadIdx.x;
    int stride = gridDim.x * blockDim.x;
    for (; i < n4; i += stride) {
        float4 a = reinterpret_cast<const float4*>(p0)[i];
        float4 b = reinterpret_cast<const float4*>(p1)[i];
        a.x += b.x; a.y += b.y; a.z += b.z; a.w += b.w;
        reinterpret_cast<float4*>(out)[i] = a;
    }
}

// ---------------------------------------------------------------------------
// TN GEMM: C[M,N] = A[M,LEN] @ B[N,LEN]^T (row stride LDK), fp16 in, fp32 acc.
// 128 threads, 4 warps 2x2, 64x64 warp tile, 3 stages (verified R7/R10 loop).
// SPLITZ: blockIdx.z selects K-slice [z*LEN, (z+1)*LEN) and partial output
// C + z*M*NN. (LEN/BKH - 2) % 3 must be 0 or 2.
// ---------------------------------------------------------------------------
template <int LEN, int LDK, int NN, bool RELUSQ, bool SPLITZ>
__global__ __launch_bounds__(128, 2)
void gemm_h(const __half* __restrict__ A, const __half* __restrict__ B,
            void* __restrict__ Cv) {
    extern __shared__ char smem[];
    const uint32_t sb = (uint32_t)__cvta_generic_to_shared(smem);

    const int tid = threadIdx.x;
    const int lane = tid & 31;
    const int warp = tid >> 5;
    const int wm = warp >> 1;
    const int wn = warp & 1;
    const int bm = blockIdx.y;
    const int bn = blockIdx.x;
    const int kz = SPLITZ ? (int)blockIdx.z : 0;

    // ---- loader geometry (verified) ----
    const int lrow = tid >> 3;
    const int lc = tid & 7;
    const uint32_t lswz = (uint32_t)((lc ^ (lrow & 7)) << 4);
    const __half* aP = A + (size_t)(bm * BM + lrow) * LDK + kz * LEN + lc * 8;
    const __half* bP = B + (size_t)(bn * BN + lrow) * LDK + kz * LEN + lc * 8;
    const uint32_t lsm = lrow * 128 + lswz;

    auto load_stage = [&](uint32_t stg_off, const __half* ag, const __half* bg) {
        uint32_t as = sb + stg_off + lsm;
        uint32_t bs = as + STAGE_A;
        #pragma unroll
        for (int i = 0; i < 8; i++)
            cp16(as + i * (16 * 128), ag + i * (16 * LDK));
        #pragma unroll
        for (int i = 0; i < 8; i++)
            cp16(bs + i * (16 * 128), bg + i * (16 * LDK));
        cp_commit();
    };

    // ---- ldmatrix per-lane geometry (verified) ----
    const int trow = lane & 7;
    const int tile = lane >> 3;
    const int t01 = tile & 1;
    const int t2 = tile >> 1;
    const uint32_t Aboff = (uint32_t)((wm * 64 + t01 * 8 + trow) * 128);
    const uint32_t Bboff = (uint32_t)(STAGE_A + (wn * 64 + t01 * 8 + trow) * 128);
    uint32_t swz[4];
    #pragma unroll
    for (int kk = 0; kk < 4; kk++)
        swz[kk] = (uint32_t)((((2 * kk + t2) ^ trow)) << 4);

    float c[4][8][4];
    #pragma unroll
    for (int mi = 0; mi < 4; mi++)
        #pragma unroll
        for (int ni = 0; ni < 8; ni++)
            #pragma unroll
            for (int r = 0; r < 4; r++) c[mi][ni][r] = 0.f;

    constexpr int KT = LEN / BKH;
    constexpr int REM = (KT - 2) % 3;
    static_assert(REM == 0 || REM == 2, "tail handles rem 0 or 2");

    uint32_t fa[2][4][4];
    uint32_t fb[2][8][2];

    auto loadfrag = [&](int buf, uint32_t stgA, uint32_t stgB, uint32_t sz) {
        #pragma unroll
        for (int mi = 0; mi < 4; mi++)
            ldsm4(fa[buf][mi][0], fa[buf][mi][1], fa[buf][mi][2], fa[buf][mi][3],
                  stgA + mi * 2048 + sz);
        #pragma unroll
        for (int nb = 0; nb < 4; nb++) {
            uint32_t r0, r1, r2, r3;
            ldsm4(r0, r1, r2, r3, stgB + nb * 2048 + sz);
            fb[buf][2 * nb][0] = r0; fb[buf][2 * nb][1] = r2;
            fb[buf][2 * nb + 1][0] = r1; fb[buf][2 * nb + 1][1] = r3;
        }
    };
    auto mmablock = [&](int buf) {
        #pragma unroll
        for (int mi = 0; mi < 4; mi++)
            #pragma unroll
            for (int ni = 0; ni < 8; ni++)
                mma16(c[mi][ni], fa[buf][mi], fb[buf][ni]);
    };

    // prologue: stages 0,1 <- tiles 0,1
    load_stage(0, aP, bP);
    load_stage(STAGE_BYTES, aP + BKH, bP + BKH);
    const __half* apre = aP + 2 * BKH;
    const __half* bpre = bP + 2 * BKH;

    auto step = [&](uint32_t stg_off, uint32_t nxt_off, bool preload, bool last) {
        if (last) cp_wait<0>(); else cp_wait<1>();
        __syncthreads();
        const uint32_t stgA = sb + stg_off + Aboff;
        const uint32_t stgB = sb + stg_off + Bboff;
        loadfrag(0, stgA, stgB, swz[0]);
        if (preload) {
            load_stage(nxt_off, apre, bpre);
            apre += BKH; bpre += BKH;
        }
        loadfrag(1, stgA, stgB, swz[1]);
        mmablock(0);
        loadfrag(0, stgA, stgB, swz[2]);
        mmablock(1);
        loadfrag(1, stgA, stgB, swz[3]);
        mmablock(0);
        mmablock(1);
    };

    constexpr uint32_t S0 = 0, S1 = STAGE_BYTES, S2 = 2 * STAGE_BYTES;
    constexpr int T = (KT - 2) / 3;          // full preload triples
    #pragma unroll 1
    for (int t = 0; t < T; t++) {
        step(S0, S2, true, false);
        step(S1, S0, true, false);
        step(S2, S1, true, false);
    }
    if constexpr (REM == 2) {
        // two more preload steps (stages 0,1), then finals at stages 2,0
        step(S0, S2, true, false);
        step(S1, S0, true, false);
        step(S2, S1, false, false);
        step(S0, S1, false, true);
    } else {
        // finals at stages 0,1
        step(S0, S2, false, false);
        step(S1, S0, false, true);
    }

    // ---- epilogue ----
    const int g = lane >> 2;
    const int q = lane & 3;
    const int row0 = bm * BM + wm * 64 + g;
    const int col0 = bn * BN + wn * 64 + q * 2;

    if (RELUSQ) {
        __half* C = (__half*)Cv;
        #pragma unroll
        for (int mi = 0; mi < 4; mi++) {
            #pragma unroll
            for (int ni = 0; ni < 8; ni++) {
                float v0 = fmaxf(c[mi][ni][0], 0.f); v0 *= v0;
                float v1 = fmaxf(c[mi][ni][1], 0.f); v1 *= v1;
                float v2 = fmaxf(c[mi][ni][2], 0.f); v2 *= v2;
                float v3 = fmaxf(c[mi][ni][3], 0.f); v3 *= v3;
                int r = row0 + mi * 16;
                int cc = col0 + ni * 8;
                *reinterpret_cast<__half2*>(C + (size_t)r * NN + cc) = __floats2half2_rn(v0, v1);
                *reinterpret_cast<__half2*>(C + (size_t)(r + 8) * NN + cc) = __floats2half2_rn(v2, v3);
            }
        }
    } else {
        float* C = (float*)Cv + (SPLITZ ? (size_t)kz * (8192ull * (size_t)NN) : 0);
        #pragma unroll
        for (int mi = 0; mi < 4; mi++) {
            #pragma unroll
            for (int ni = 0; ni < 8; ni++) {
                int r = row0 + mi * 16;
                int cc = col0 + ni * 8;
                *reinterpret_cast<float2*>(C + (size_t)r * NN + cc) =
                    make_float2(c[mi][ni][0], c[mi][ni][1]);
                *reinterpret_cast<float2*>(C + (size_t)(r + 8) * NN + cc) =
                    make_float2(c[mi][ni][2], c[mi][ni][3]);
            }
        }
    }
}

// ---------------------------------------------------------------------------

extern "C" void kernel_launch(void* const* d_in, const int* in_sizes, int n_in,
                              void* d_out, int out_size) {
    const float* x     = (const float*)d_in[0];   // [8192, 2048]
    const float* wfc   = (const float*)d_in[1];   // [8192, 2048]
    const float* wproj = (const float*)d_in[2];   // [2048, 8192]
    float* out = (float*)d_out;                    // [8192, 2048]

    __half *xh, *wfcq, *wpjq, *h2;
    float *part;
    cudaGetSymbolAddress((void**)&xh, g_xh);
    cudaGetSymbolAddress((void**)&wfcq, g_wfc);
    cudaGetSymbolAddress((void**)&wpjq, g_wpj);
    cudaGetSymbolAddress((void**)&h2, g_h2);
    cudaGetSymbolAddress((void**)&part, g_part);

    void (*g1)(const __half*, const __half*, void*) = gemm_h<2048, 2048, 8192, true, false>;
    void (*g2)(const __half*, const __half*, void*) = gemm_h<4096, 8192, 2048, false, true>;
    cudaFuncSetAttribute(g1, cudaFuncAttributeMaxDynamicSharedMemorySize, SMEM_TOTAL);
    cudaFuncSetAttribute(g2, cudaFuncAttributeMaxDynamicSharedMemorySize, SMEM_TOTAL);

    // 1. fused prep: quant wfc + quant wproj + x->fp16
    prep_kernel<<<2 * QB_CTAS + CONV_CTAS, 256>>>(wfc, wproj, x, wfcq, wpjq, xh);

    // 2. h2 = half(relu(x @ wfcq^T)^2)
    {
        dim3 grid(8192 / BN, 8192 / BM);          // (64, 64)
        gemm_h<2048, 2048, 8192, true, false><<<grid, 128, SMEM_TOTAL>>>(xh, wfcq, (void*)h2);
    }

    // 3. split-K=2: part[z] = h2[:, z*4096:(z+1)*4096] @ wpjq[:, same]^T
    {
        dim3 grid(2048 / BN, 8192 / BM, 2);       // (16, 64, 2)
        gemm_h<4096, 8192, 2048, false, true><<<grid, 128, SMEM_TOTAL>>>(h2, wpjq, (void*)part);
    }

    // 4. out = part0 + part1
    reduce_kernel<<<2048, 256>>>(part, part + 8192ull * 2048, out, (8192 * 2048) / 4);
}

// round 12
// speedup vs baseline: 1.0195x; 1.0195x over previous
#include <cuda_runtime.h>
#include <cuda_fp16.h>
#include <cstdint>
#include <cstddef>

// ---------------------------------------------------------------------------
// out = (relu(x @ qdq(w_fc)^T)^2) @ qdq(w_proj)^T
// M=8192, K1=2048, N1=8192 ; K2=8192, N2=2048
// Round 12: consolidation. GEMM1+GEMM2 = exact verified R7/R10 mainloop
// (128x128 CTA, 2 CTA/SM, 64x64 warp tiles, 3-stage cp.async, unroll-by-3,
// frag double-buffering). Split-K reverted (R11: reduce cost > tail gain).
// Prep = verified fused single launch (quant wfc + quant wproj + x->fp16).
// ---------------------------------------------------------------------------

#define BM 128
#define BN 128
#define BKH 64                    // halves per k-tile (128 B rows)
#define STAGE_A (BM * 128)        // bytes
#define STAGE_B (BN * 128)
#define STAGE_BYTES (STAGE_A + STAGE_B)          // 32768
#define SMEM_TOTAL (3 * STAGE_BYTES)             // 98304

// Scratch (allocation-free)
__device__ __align__(256) __half g_xh[8192ull * 2048];
__device__ __align__(256) __half g_wfc[8192ull * 2048];
__device__ __align__(256) __half g_wpj[2048ull * 8192];
__device__ __align__(256) __half g_h2[8192ull * 8192];

// ---------------------------------------------------------------------------
__device__ __forceinline__ void cp16(uint32_t s, const void* g) {
    asm volatile("cp.async.cg.shared.global [%0], [%1], 16;" :: "r"(s), "l"(g));
}
__device__ __forceinline__ void cp_commit() { asm volatile("cp.async.commit_group;"); }
template <int N>
__device__ __forceinline__ void cp_wait() { asm volatile("cp.async.wait_group %0;" :: "n"(N)); }

__device__ __forceinline__ void ldsm4(uint32_t& r0, uint32_t& r1, uint32_t& r2,
                                      uint32_t& r3, uint32_t addr) {
    asm volatile("ldmatrix.sync.aligned.m8n8.x4.shared.b16 {%0,%1,%2,%3}, [%4];"
                 : "=r"(r0), "=r"(r1), "=r"(r2), "=r"(r3) : "r"(addr));
}

__device__ __forceinline__ void mma16(float c[4], const uint32_t a[4], const uint32_t b[2]) {
    asm volatile(
        "mma.sync.aligned.m16n8k16.row.col.f32.f16.f16.f32 "
        "{%0,%1,%2,%3}, {%4,%5,%6,%7}, {%8,%9}, {%0,%1,%2,%3};"
        : "+f"(c[0]), "+f"(c[1]), "+f"(c[2]), "+f"(c[3])
        : "r"(a[0]), "r"(a[1]), "r"(a[2]), "r"(a[3]), "r"(b[0]), "r"(b[1]));
}

// ---------------------------------------------------------------------------
// Quant body (verified R10/R11 bit-exact): warp per 64-block, ILP butterfly.
// ---------------------------------------------------------------------------
__device__ __forceinline__ void quant_block(const float* __restrict__ w,
                                            __half* __restrict__ wq,
                                            int b, int lane) {
    const float* p = w + (size_t)b * 64;
    float w0 = p[lane];
    float w1 = p[lane + 32];

    float amax = fmaxf(fabsf(w0), fabsf(w1));
    #pragma unroll
    for (int o = 16; o; o >>= 1) amax = fmaxf(amax, __shfl_xor_sync(0xffffffffu, amax, o));

    float am = fmaxf(amax, 1e-8f);
    float base = __fdiv_rn(am, 15.0f);
    float invb = __fdiv_rn(15.0f, am);

    const float shr[16] = {0.4f, 0.44f, 0.48f, 0.52f, 0.56f, 0.6f, 0.64f, 0.68f,
                           0.72f, 0.76f, 0.8f, 0.84f, 0.88f, 0.92f, 0.96f, 1.0f};
    const float ishr[16] = {2.5f, 1.0f/0.44f, 1.0f/0.48f, 1.0f/0.52f,
                            1.0f/0.56f, 1.0f/0.6f, 1.0f/0.64f, 1.0f/0.68f,
                            1.0f/0.72f, 1.0f/0.76f, 1.25f, 1.0f/0.84f,
                            1.0f/0.88f, 1.0f/0.92f, 1.0f/0.96f, 1.0f};

    float e[16];
    #pragma unroll
    for (int i = 0; i < 16; i++) {
        float s = base * shr[i];
        float inv = invb * ishr[i];
        float q0 = fminf(fmaxf(rintf(w0 * inv), -15.f), 15.f);
        float q1 = fminf(fmaxf(rintf(w1 * inv), -15.f), 15.f);
        float d0 = fmaf(q0, s, -w0);
        float d1 = fmaf(q1, s, -w1);
        e[i] = fmaf(d0, d0, d1 * d1);
    }
    #pragma unroll
    for (int o = 16; o; o >>= 1) {
        #pragma unroll
        for (int i = 0; i < 16; i++)
            e[i] += __shfl_xor_sync(0xffffffffu, e[i], o);
    }
    float best_err = e[0];
    int idx = 0;
    #pragma unroll
    for (int i = 1; i < 16; i++)
        if (e[i] < best_err) { best_err = e[i]; idx = i; }

    float best_scale = base * shr[idx];
    float best_inv = invb * ishr[idx];
    float q0 = fminf(fmaxf(rintf(w0 * best_inv), -15.f), 15.f);
    float q1 = fminf(fmaxf(rintf(w1 * best_inv), -15.f), 15.f);
    wq[(size_t)b * 64 + lane]      = __float2half_rn(q0 * best_scale);
    wq[(size_t)b * 64 + lane + 32] = __float2half_rn(q1 * best_scale);
}

// Fused prep: [0,QB) quant wfc, [QB,2QB) quant wproj, [2QB,2QB+CONV) x->fp16.
#define QB_CTAS 32768            // 262144 blocks / 8 per CTA
#define CONV_CTAS 2048
__global__ __launch_bounds__(256)
void prep_kernel(const float* __restrict__ wfc, const float* __restrict__ wpj,
                 const float* __restrict__ x,
                 __half* __restrict__ wfcq, __half* __restrict__ wpjq,
                 __half* __restrict__ xh) {
    int cta = blockIdx.x;
    if (cta < 2 * QB_CTAS) {
        const float* w = (cta < QB_CTAS) ? wfc : wpj;
        __half* wq = (cta < QB_CTAS) ? wfcq : wpjq;
        int base_cta = (cta < QB_CTAS) ? cta : cta - QB_CTAS;
        int b = base_cta * 8 + (threadIdx.x >> 5);
        quant_block(w, wq, b, threadIdx.x & 31);
    } else {
        int bid = cta - 2 * QB_CTAS;
        const int n4 = (8192 * 2048) / 4;
        int i = bid * 256 + threadIdx.x;
        const int stride = CONV_CTAS * 256;
        for (; i < n4; i += stride) {
            float4 v = reinterpret_cast<const float4*>(x)[i];
            __half2 h0 = __floats2half2_rn(v.x, v.y);
            __half2 h1 = __floats2half2_rn(v.z, v.w);
            uint2 pk;
            pk.x = *reinterpret_cast<uint32_t*>(&h0);
            pk.y = *reinterpret_cast<uint32_t*>(&h1);
            reinterpret_cast<uint2*>(xh)[i] = pk;
        }
    }
}

// ---------------------------------------------------------------------------
// TN GEMM: C[M,N] = A[M,K] @ B[N,K]^T, fp16 in, fp32 accum.
// 128 threads, 4 warps 2x2, 64x64 warp tile, 3 stages (verified R7/R10 loop).
// (K/BKH - 2) % 3 must be 0 or 2 (K=2048 -> 30%3=0, K=8192 -> 126%3=0).
// ---------------------------------------------------------------------------
template <int K, int NN, bool RELUSQ>
__global__ __launch_bounds__(128, 2)
void gemm_h(const __half* __restrict__ A, const __half* __restrict__ B,
            void* __restrict__ Cv) {
    extern __shared__ char smem[];
    const uint32_t sb = (uint32_t)__cvta_generic_to_shared(smem);

    const int tid = threadIdx.x;
    const int lane = tid & 31;
    const int warp = tid >> 5;
    const int wm = warp >> 1;
    const int wn = warp & 1;
    const int bm = blockIdx.y;
    const int bn = blockIdx.x;

    // ---- loader geometry (verified R5-R10 mapping) ----
    const int lrow = tid >> 3;
    const int lc = tid & 7;
    const uint32_t lswz = (uint32_t)((lc ^ (lrow & 7)) << 4);
    const __half* aP = A + (size_t)(bm * BM + lrow) * K + lc * 8;
    const __half* bP = B + (size_t)(bn * BN + lrow) * K + lc * 8;
    const uint32_t lsm = lrow * 128 + lswz;

    auto load_stage = [&](uint32_t stg_off, const __half* ag, const __half* bg) {
        uint32_t as = sb + stg_off + lsm;
        uint32_t bs = as + STAGE_A;
        #pragma unroll
        for (int i = 0; i < 8; i++)
            cp16(as + i * (16 * 128), ag + i * (16 * K));
        #pragma unroll
        for (int i = 0; i < 8; i++)
            cp16(bs + i * (16 * 128), bg + i * (16 * K));
        cp_commit();
    };

    // ---- ldmatrix per-lane geometry (verified) ----
    const int trow = lane & 7;
    const int tile = lane >> 3;
    const int t01 = tile & 1;
    const int t2 = tile >> 1;
    const uint32_t Aboff = (uint32_t)((wm * 64 + t01 * 8 + trow) * 128);
    const uint32_t Bboff = (uint32_t)(STAGE_A + (wn * 64 + t01 * 8 + trow) * 128);
    uint32_t swz[4];
    #pragma unroll
    for (int kk = 0; kk < 4; kk++)
        swz[kk] = (uint32_t)((((2 * kk + t2) ^ trow)) << 4);

    float c[4][8][4];
    #pragma unroll
    for (int mi = 0; mi < 4; mi++)
        #pragma unroll
        for (int ni = 0; ni < 8; ni++)
            #pragma unroll
            for (int r = 0; r < 4; r++) c[mi][ni][r] = 0.f;

    constexpr int KT = K / BKH;
    constexpr int REM = (KT - 2) % 3;
    static_assert(REM == 0, "tail assumes KT mod 3 == 2");

    uint32_t fa[2][4][4];
    uint32_t fb[2][8][2];

    auto loadfrag = [&](int buf, uint32_t stgA, uint32_t stgB, uint32_t sz) {
        #pragma unroll
        for (int mi = 0; mi < 4; mi++)
            ldsm4(fa[buf][mi][0], fa[buf][mi][1], fa[buf][mi][2], fa[buf][mi][3],
                  stgA + mi * 2048 + sz);
        #pragma unroll
        for (int nb = 0; nb < 4; nb++) {
            uint32_t r0, r1, r2, r3;
            ldsm4(r0, r1, r2, r3, stgB + nb * 2048 + sz);
            fb[buf][2 * nb][0] = r0; fb[buf][2 * nb][1] = r2;
            fb[buf][2 * nb + 1][0] = r1; fb[buf][2 * nb + 1][1] = r3;
        }
    };
    auto mmablock = [&](int buf) {
        #pragma unroll
        for (int mi = 0; mi < 4; mi++)
            #pragma unroll
            for (int ni = 0; ni < 8; ni++)
                mma16(c[mi][ni], fa[buf][mi], fb[buf][ni]);
    };

    // prologue: stages 0,1 <- tiles 0,1
    load_stage(0, aP, bP);
    load_stage(STAGE_BYTES, aP + BKH, bP + BKH);
    const __half* apre = aP + 2 * BKH;   // src for tile kt+2
    const __half* bpre = bP + 2 * BKH;

    // one step: consume stage at stg_off; optionally preload the tile two
    // ahead into nxt_off. last=true waits for all outstanding groups.
    auto step = [&](uint32_t stg_off, uint32_t nxt_off, bool preload, bool last) {
        if (last) cp_wait<0>(); else cp_wait<1>();
        __syncthreads();
        const uint32_t stgA = sb + stg_off + Aboff;
        const uint32_t stgB = sb + stg_off + Bboff;
        loadfrag(0, stgA, stgB, swz[0]);
        if (preload) {
            load_stage(nxt_off, apre, bpre);
            apre += BKH; bpre += BKH;
        }
        loadfrag(1, stgA, stgB, swz[1]);
        mmablock(0);
        loadfrag(0, stgA, stgB, swz[2]);
        mmablock(1);
        loadfrag(1, stgA, stgB, swz[3]);
        mmablock(0);
        mmablock(1);
    };

    constexpr uint32_t S0 = 0, S1 = STAGE_BYTES, S2 = 2 * STAGE_BYTES;
    constexpr int T = (KT - 2) / 3;          // full preload triples
    #pragma unroll 1
    for (int t = 0; t < T; t++) {
        step(S0, S2, true, false);
        step(S1, S0, true, false);
        step(S2, S1, true, false);
    }
    // tail: exactly 2 tiles (stages 0,1), no preload
    step(S0, S2, false, false);
    step(S1, S0, false, true);

    // ---- epilogue ----
    const int g = lane >> 2;
    const int q = lane & 3;
    const int row0 = bm * BM + wm * 64 + g;
    const int col0 = bn * BN + wn * 64 + q * 2;

    if (RELUSQ) {
        __half* C = (__half*)Cv;
        #pragma unroll
        for (int mi = 0; mi < 4; mi++) {
            #pragma unroll
            for (int ni = 0; ni < 8; ni++) {
                float v0 = fmaxf(c[mi][ni][0], 0.f); v0 *= v0;
                float v1 = fmaxf(c[mi][ni][1], 0.f); v1 *= v1;
                float v2 = fmaxf(c[mi][ni][2], 0.f); v2 *= v2;
                float v3 = fmaxf(c[mi][ni][3], 0.f); v3 *= v3;
                int r = row0 + mi * 16;
                int cc = col0 + ni * 8;
                *reinterpret_cast<__half2*>(C + (size_t)r * NN + cc) = __floats2half2_rn(v0, v1);
                *reinterpret_cast<__half2*>(C + (size_t)(r + 8) * NN + cc) = __floats2half2_rn(v2, v3);
            }
        }
    } else {
        float* C = (float*)Cv;
        #pragma unroll
        for (int mi = 0; mi < 4; mi++) {
            #pragma unroll
            for (int ni = 0; ni < 8; ni++) {
                int r = row0 + mi * 16;
                int cc = col0 + ni * 8;
                *reinterpret_cast<float2*>(C + (size_t)r * NN + cc) =
                    make_float2(c[mi][ni][0], c[mi][ni][1]);
                *reinterpret_cast<float2*>(C + (size_t)(r + 8) * NN + cc) =
                    make_float2(c[mi][ni][2], c[mi][ni][3]);
            }
        }
    }
}

// ---------------------------------------------------------------------------

extern "C" void kernel_launch(void* const* d_in, const int* in_sizes, int n_in,
                              void* d_out, int out_size) {
    const float* x     = (const float*)d_in[0];   // [8192, 2048]
    const float* wfc   = (const float*)d_in[1];   // [8192, 2048]
    const float* wproj = (const float*)d_in[2];   // [2048, 8192]
    float* out = (float*)d_out;                    // [8192, 2048]

    __half *xh, *wfcq, *wpjq, *h2;
    cudaGetSymbolAddress((void**)&xh, g_xh);
    cudaGetSymbolAddress((void**)&wfcq, g_wfc);
    cudaGetSymbolAddress((void**)&wpjq, g_wpj);
    cudaGetSymbolAddress((void**)&h2, g_h2);

    void (*g1)(const __half*, const __half*, void*) = gemm_h<2048, 8192, true>;
    void (*g2)(const __half*, const __half*, void*) = gemm_h<8192, 2048, false>;
    cudaFuncSetAttribute(g1, cudaFuncAttributeMaxDynamicSharedMemorySize, SMEM_TOTAL);
    cudaFuncSetAttribute(g2, cudaFuncAttributeMaxDynamicSharedMemorySize, SMEM_TOTAL);

    // 1. fused prep: quant wfc + quant wproj + x->fp16 (one launch)
    prep_kernel<<<2 * QB_CTAS + CONV_CTAS, 256>>>(wfc, wproj, x, wfcq, wpjq, xh);

    // 2. h2 = half(relu(x @ wfcq^T)^2)
    {
        dim3 grid(8192 / BN, 8192 / BM);          // (64, 64)
        gemm_h<2048, 8192, true><<<grid, 128, SMEM_TOTAL>>>(xh, wfcq, (void*)h2);
    }

    // 3. out = h2 @ wpjq^T   (fp32 out)
    {
        dim3 grid(2048 / BN, 8192 / BM);          // (16, 64)
        gemm_h<8192, 2048, false><<<grid, 128, SMEM_TOTAL>>>(h2, wpjq, (void*)out);
    }
}

// round 13
// speedup vs baseline: 1.1223x; 1.1009x over previous
#include <cuda_runtime.h>
#include <cuda_fp16.h>
#include <cstdint>
#include <cstddef>

// ---------------------------------------------------------------------------
// out = (relu(x @ qdq(w_fc)^T)^2) @ qdq(w_proj)^T
// M=8192, K1=2048, N1=8192 ; K2=8192, N2=2048
// Round 13: GEMMs = exact verified R7/R10/R12 mainloop. NEW prep: quant is
// thread-per-64-block (smem-staged, conflict-free 68-float stride), zero
// shuffles, ~210 vs ~330 warp-instr equivalents per block. Prep was measured
// 329us issue-bound (81%) in R12 -> target ~215us.
// ---------------------------------------------------------------------------

#define BM 128
#define BN 128
#define BKH 64                    // halves per k-tile (128 B rows)
#define STAGE_A (BM * 128)        // bytes
#define STAGE_B (BN * 128)
#define STAGE_BYTES (STAGE_A + STAGE_B)          // 32768
#define SMEM_TOTAL (3 * STAGE_BYTES)             // 98304

// Scratch (allocation-free)
__device__ __align__(256) __half g_xh[8192ull * 2048];
__device__ __align__(256) __half g_wfc[8192ull * 2048];
__device__ __align__(256) __half g_wpj[2048ull * 8192];
__device__ __align__(256) __half g_h2[8192ull * 8192];

// shrink tables (same fp32 literals as verified rounds; const-bank for the
// partially-unrolled loop)
__constant__ float c_shr[16] = {0.4f, 0.44f, 0.48f, 0.52f, 0.56f, 0.6f, 0.64f,
                                0.68f, 0.72f, 0.76f, 0.8f, 0.84f, 0.88f, 0.92f,
                                0.96f, 1.0f};
__constant__ float c_ishr[16] = {2.5f, 1.0f/0.44f, 1.0f/0.48f, 1.0f/0.52f,
                                 1.0f/0.56f, 1.0f/0.6f, 1.0f/0.64f, 1.0f/0.68f,
                                 1.0f/0.72f, 1.0f/0.76f, 1.25f, 1.0f/0.84f,
                                 1.0f/0.88f, 1.0f/0.92f, 1.0f/0.96f, 1.0f};

// ---------------------------------------------------------------------------
__device__ __forceinline__ void cp16(uint32_t s, const void* g) {
    asm volatile("cp.async.cg.shared.global [%0], [%1], 16;" :: "r"(s), "l"(g));
}
__device__ __forceinline__ void cp_commit() { asm volatile("cp.async.commit_group;"); }
template <int N>
__device__ __forceinline__ void cp_wait() { asm volatile("cp.async.wait_group %0;" :: "n"(N)); }

__device__ __forceinline__ void ldsm4(uint32_t& r0, uint32_t& r1, uint32_t& r2,
                                      uint32_t& r3, uint32_t addr) {
    asm volatile("ldmatrix.sync.aligned.m8n8.x4.shared.b16 {%0,%1,%2,%3}, [%4];"
                 : "=r"(r0), "=r"(r1), "=r"(r2), "=r"(r3) : "r"(addr));
}

__device__ __forceinline__ void mma16(float c[4], const uint32_t a[4], const uint32_t b[2]) {
    asm volatile(
        "mma.sync.aligned.m16n8k16.row.col.f32.f16.f16.f32 "
        "{%0,%1,%2,%3}, {%4,%5,%6,%7}, {%8,%9}, {%0,%1,%2,%3};"
        : "+f"(c[0]), "+f"(c[1]), "+f"(c[2]), "+f"(c[3])
        : "r"(a[0]), "r"(a[1]), "r"(a[2]), "r"(a[3]), "r"(b[0]), "r"(b[1]));
}

// ---------------------------------------------------------------------------
// Thread-per-block quant. One warp handles 32 consecutive 64-elem blocks:
// stage 8KB coalesced into padded smem (68-float block stride: STS.128 and
// LDS.128 both conflict-free), each lane then owns one whole block.
// ---------------------------------------------------------------------------
#define QPAD 68
__device__ __forceinline__ void quant_warp(const float* __restrict__ w,
                                           __half* __restrict__ wq,
                                           int blk0, int lane,
                                           float* __restrict__ swarp) {
    // ---- stage 32 blocks (2048 floats) coalesced ----
    const float4* src = reinterpret_cast<const float4*>(w + (size_t)blk0 * 64);
    #pragma unroll
    for (int j = 0; j < 16; j++) {
        float4 v = src[j * 32 + lane];
        int blk = 2 * j + (lane >> 4);
        int chunk = lane & 15;
        *reinterpret_cast<float4*>(swarp + blk * QPAD + chunk * 4) = v;
    }
    __syncwarp();

    // ---- each lane loads its own block ----
    float4 d[16];
    const float* my = swarp + lane * QPAD;
    #pragma unroll
    for (int j = 0; j < 16; j++)
        d[j] = *reinterpret_cast<const float4*>(my + 4 * j);

    // ---- amax (max-tree; order-insensitive) ----
    float mj[16];
    #pragma unroll
    for (int j = 0; j < 16; j++)
        mj[j] = fmaxf(fmaxf(fabsf(d[j].x), fabsf(d[j].y)),
                      fmaxf(fabsf(d[j].z), fabsf(d[j].w)));
    #pragma unroll
    for (int st = 8; st; st >>= 1)
        #pragma unroll
        for (int k = 0; k < 8; k++)
            if (k < st) mj[k] = fmaxf(mj[k], mj[k + st]);
    float am = fmaxf(mj[0], 1e-8f);

    float base = __fdiv_rn(am, 15.0f);
    float invb = __fdiv_rn(15.0f, am);

    // ---- shrink search (unroll 2: keeps code in L1.5 I$) ----
    float best_err = __int_as_float(0x7f800000);
    float bs = base, binv = invb;
    #pragma unroll 2
    for (int i = 0; i < 16; i++) {
        float s = base * c_shr[i];
        float inv = invb * c_ishr[i];
        float a0 = 0.f, a1 = 0.f, a2 = 0.f, a3 = 0.f;
        #pragma unroll
        for (int j = 0; j < 16; j++) {
            float q, dd;
            q = fminf(fmaxf(rintf(d[j].x * inv), -15.f), 15.f);
            dd = fmaf(q, s, -d[j].x); a0 = fmaf(dd, dd, a0);
            q = fminf(fmaxf(rintf(d[j].y * inv), -15.f), 15.f);
            dd = fmaf(q, s, -d[j].y); a1 = fmaf(dd, dd, a1);
            q = fminf(fmaxf(rintf(d[j].z * inv), -15.f), 15.f);
            dd = fmaf(q, s, -d[j].z); a2 = fmaf(dd, dd, a2);
            q = fminf(fmaxf(rintf(d[j].w * inv), -15.f), 15.f);
            dd = fmaf(q, s, -d[j].w); a3 = fmaf(dd, dd, a3);
        }
        float e = (a0 + a1) + (a2 + a3);
        if (e < best_err) { best_err = e; bs = s; binv = inv; }  // strict <, earliest wins
    }

    // ---- dequantize with best scale, pack fp16, store own block ----
    uint4* dst = reinterpret_cast<uint4*>(wq + (size_t)(blk0 + lane) * 64);
    #pragma unroll
    for (int p = 0; p < 8; p++) {
        float4 v0 = d[2 * p], v1 = d[2 * p + 1];
        float q0 = fminf(fmaxf(rintf(v0.x * binv), -15.f), 15.f) * bs;
        float q1 = fminf(fmaxf(rintf(v0.y * binv), -15.f), 15.f) * bs;
        float q2 = fminf(fmaxf(rintf(v0.z * binv), -15.f), 15.f) * bs;
        float q3 = fminf(fmaxf(rintf(v0.w * binv), -15.f), 15.f) * bs;
        float q4 = fminf(fmaxf(rintf(v1.x * binv), -15.f), 15.f) * bs;
        float q5 = fminf(fmaxf(rintf(v1.y * binv), -15.f), 15.f) * bs;
        float q6 = fminf(fmaxf(rintf(v1.z * binv), -15.f), 15.f) * bs;
        float q7 = fminf(fmaxf(rintf(v1.w * binv), -15.f), 15.f) * bs;
        __half2 h0 = __floats2half2_rn(q0, q1);
        __half2 h1 = __floats2half2_rn(q2, q3);
        __half2 h2 = __floats2half2_rn(q4, q5);
        __half2 h3 = __floats2half2_rn(q6, q7);
        uint4 o;
        o.x = *reinterpret_cast<uint32_t*>(&h0);
        o.y = *reinterpret_cast<uint32_t*>(&h1);
        o.z = *reinterpret_cast<uint32_t*>(&h2);
        o.w = *reinterpret_cast<uint32_t*>(&h3);
        dst[p] = o;
    }
}

// Fused prep: [0,QB) quant wfc, [QB,2QB) quant wproj, rest: x->fp16.
// 128 threads/CTA; each quant CTA = 4 warps x 32 blocks = 128 blocks.
#define QB_CTAS 2048             // 262144 blocks / 128 per CTA
#define CONV_CTAS 4096
__global__ __launch_bounds__(128)
void prep_kernel(const float* __restrict__ wfc, const float* __restrict__ wpj,
                 const float* __restrict__ x,
                 __half* __restrict__ wfcq, __half* __restrict__ wpjq,
                 __half* __restrict__ xh) {
    __shared__ float stage[4][32 * QPAD];
    int cta = blockIdx.x;
    if (cta < 2 * QB_CTAS) {
        const float* w = wfc;
        __half* wq = wfcq;
        int local = cta;
        if (cta >= QB_CTAS) { w = wpj; wq = wpjq; local = cta - QB_CTAS; }
        int warp = threadIdx.x >> 5;
        int lane = threadIdx.x & 31;
        int blk0 = (local * 4 + warp) * 32;
        quant_warp(w, wq, blk0, lane, stage[warp]);
    } else {
        int bid = cta - 2 * QB_CTAS;
        const int n4 = (8192 * 2048) / 4;
        int i = bid * 128 + threadIdx.x;
        const int stride = CONV_CTAS * 128;
        for (; i < n4; i += stride) {
            float4 v = reinterpret_cast<const float4*>(x)[i];
            __half2 h0 = __floats2half2_rn(v.x, v.y);
            __half2 h1 = __floats2half2_rn(v.z, v.w);
            uint2 pk;
            pk.x = *reinterpret_cast<uint32_t*>(&h0);
            pk.y = *reinterpret_cast<uint32_t*>(&h1);
            reinterpret_cast<uint2*>(xh)[i] = pk;
        }
    }
}

// ---------------------------------------------------------------------------
// TN GEMM: C[M,N] = A[M,K] @ B[N,K]^T, fp16 in, fp32 accum.
// 128 threads, 4 warps 2x2, 64x64 warp tile, 3 stages (verified R7/R10/R12).
// ---------------------------------------------------------------------------
template <int K, int NN, bool RELUSQ>
__global__ __launch_bounds__(128, 2)
void gemm_h(const __half* __restrict__ A, const __half* __restrict__ B,
            void* __restrict__ Cv) {
    extern __shared__ char smem[];
    const uint32_t sb = (uint32_t)__cvta_generic_to_shared(smem);

    const int tid = threadIdx.x;
    const int lane = tid & 31;
    const int warp = tid >> 5;
    const int wm = warp >> 1;
    const int wn = warp & 1;
    const int bm = blockIdx.y;
    const int bn = blockIdx.x;

    const int lrow = tid >> 3;
    const int lc = tid & 7;
    const uint32_t lswz = (uint32_t)((lc ^ (lrow & 7)) << 4);
    const __half* aP = A + (size_t)(bm * BM + lrow) * K + lc * 8;
    const __half* bP = B + (size_t)(bn * BN + lrow) * K + lc * 8;
    const uint32_t lsm = lrow * 128 + lswz;

    auto load_stage = [&](uint32_t stg_off, const __half* ag, const __half* bg) {
        uint32_t as = sb + stg_off + lsm;
        uint32_t bs = as + STAGE_A;
        #pragma unroll
        for (int i = 0; i < 8; i++)
            cp16(as + i * (16 * 128), ag + i * (16 * K));
        #pragma unroll
        for (int i = 0; i < 8; i++)
            cp16(bs + i * (16 * 128), bg + i * (16 * K));
        cp_commit();
    };

    const int trow = lane & 7;
    const int tile = lane >> 3;
    const int t01 = tile & 1;
    const int t2 = tile >> 1;
    const uint32_t Aboff = (uint32_t)((wm * 64 + t01 * 8 + trow) * 128);
    const uint32_t Bboff = (uint32_t)(STAGE_A + (wn * 64 + t01 * 8 + trow) * 128);
    uint32_t swz[4];
    #pragma unroll
    for (int kk = 0; kk < 4; kk++)
        swz[kk] = (uint32_t)((((2 * kk + t2) ^ trow)) << 4);

    float c[4][8][4];
    #pragma unroll
    for (int mi = 0; mi < 4; mi++)
        #pragma unroll
        for (int ni = 0; ni < 8; ni++)
            #pragma unroll
            for (int r = 0; r < 4; r++) c[mi][ni][r] = 0.f;

    constexpr int KT = K / BKH;
    static_assert((KT - 2) % 3 == 0, "loop needs KT mod 3 == 2");

    uint32_t fa[2][4][4];
    uint32_t fb[2][8][2];

    auto loadfrag = [&](int buf, uint32_t stgA, uint32_t stgB, uint32_t sz) {
        #pragma unroll
        for (int mi = 0; mi < 4; mi++)
            ldsm4(fa[buf][mi][0], fa[buf][mi][1], fa[buf][mi][2], fa[buf][mi][3],
                  stgA + mi * 2048 + sz);
        #pragma unroll
        for (int nb = 0; nb < 4; nb++) {
            uint32_t r0, r1, r2, r3;
            ldsm4(r0, r1, r2, r3, stgB + nb * 2048 + sz);
            fb[buf][2 * nb][0] = r0; fb[buf][2 * nb][1] = r2;
            fb[buf][2 * nb + 1][0] = r1; fb[buf][2 * nb + 1][1] = r3;
        }
    };
    auto mmablock = [&](int buf) {
        #pragma unroll
        for (int mi = 0; mi < 4; mi++)
            #pragma unroll
            for (int ni = 0; ni < 8; ni++)
                mma16(c[mi][ni], fa[buf][mi], fb[buf][ni]);
    };

    load_stage(0, aP, bP);
    load_stage(STAGE_BYTES, aP + BKH, bP + BKH);
    const __half* apre = aP + 2 * BKH;
    const __half* bpre = bP + 2 * BKH;

    auto step = [&](uint32_t stg_off, uint32_t nxt_off, bool preload, bool last) {
        if (last) cp_wait<0>(); else cp_wait<1>();
        __syncthreads();
        const uint32_t stgA = sb + stg_off + Aboff;
        const uint32_t stgB = sb + stg_off + Bboff;
        loadfrag(0, stgA, stgB, swz[0]);
        if (preload) {
            load_stage(nxt_off, apre, bpre);
            apre += BKH; bpre += BKH;
        }
        loadfrag(1, stgA, stgB, swz[1]);
        mmablock(0);
        loadfrag(0, stgA, stgB, swz[2]);
        mmablock(1);
        loadfrag(1, stgA, stgB, swz[3]);
        mmablock(0);
        mmablock(1);
    };

    constexpr uint32_t S0 = 0, S1 = STAGE_BYTES, S2 = 2 * STAGE_BYTES;
    constexpr int T = (KT - 2) / 3;
    #pragma unroll 1
    for (int t = 0; t < T; t++) {
        step(S0, S2, true, false);
        step(S1, S0, true, false);
        step(S2, S1, true, false);
    }
    step(S0, S2, false, false);
    step(S1, S0, false, true);

    // ---- epilogue ----
    const int g = lane >> 2;
    const int q = lane & 3;
    const int row0 = bm * BM + wm * 64 + g;
    const int col0 = bn * BN + wn * 64 + q * 2;

    if (RELUSQ) {
        __half* C = (__half*)Cv;
        #pragma unroll
        for (int mi = 0; mi < 4; mi++) {
            #pragma unroll
            for (int ni = 0; ni < 8; ni++) {
                float v0 = fmaxf(c[mi][ni][0], 0.f); v0 *= v0;
                float v1 = fmaxf(c[mi][ni][1], 0.f); v1 *= v1;
                float v2 = fmaxf(c[mi][ni][2], 0.f); v2 *= v2;
                float v3 = fmaxf(c[mi][ni][3], 0.f); v3 *= v3;
                int r = row0 + mi * 16;
                int cc = col0 + ni * 8;
                *reinterpret_cast<__half2*>(C + (size_t)r * NN + cc) = __floats2half2_rn(v0, v1);
                *reinterpret_cast<__half2*>(C + (size_t)(r + 8) * NN + cc) = __floats2half2_rn(v2, v3);
            }
        }
    } else {
        float* C = (float*)Cv;
        #pragma unroll
        for (int mi = 0; mi < 4; mi++) {
            #pragma unroll
            for (int ni = 0; ni < 8; ni++) {
                int r = row0 + mi * 16;
                int cc = col0 + ni * 8;
                *reinterpret_cast<float2*>(C + (size_t)r * NN + cc) =
                    make_float2(c[mi][ni][0], c[mi][ni][1]);
                *reinterpret_cast<float2*>(C + (size_t)(r + 8) * NN + cc) =
                    make_float2(c[mi][ni][2], c[mi][ni][3]);
            }
        }
    }
}

// ---------------------------------------------------------------------------

extern "C" void kernel_launch(void* const* d_in, const int* in_sizes, int n_in,
                              void* d_out, int out_size) {
    const float* x     = (const float*)d_in[0];   // [8192, 2048]
    const float* wfc   = (const float*)d_in[1];   // [8192, 2048]
    const float* wproj = (const float*)d_in[2];   // [2048, 8192]
    float* out = (float*)d_out;                    // [8192, 2048]

    __half *xh, *wfcq, *wpjq, *h2;
    cudaGetSymbolAddress((void**)&xh, g_xh);
    cudaGetSymbolAddress((void**)&wfcq, g_wfc);
    cudaGetSymbolAddress((void**)&wpjq, g_wpj);
    cudaGetSymbolAddress((void**)&h2, g_h2);

    void (*g1)(const __half*, const __half*, void*) = gemm_h<2048, 8192, true>;
    void (*g2)(const __half*, const __half*, void*) = gemm_h<8192, 2048, false>;
    cudaFuncSetAttribute(g1, cudaFuncAttributeMaxDynamicSharedMemorySize, SMEM_TOTAL);
    cudaFuncSetAttribute(g2, cudaFuncAttributeMaxDynamicSharedMemorySize, SMEM_TOTAL);

    // 1. fused prep: quant wfc + quant wproj + x->fp16 (one launch)
    prep_kernel<<<2 * QB_CTAS + CONV_CTAS, 128>>>(wfc, wproj, x, wfcq, wpjq, xh);

    // 2. h2 = half(relu(x @ wfcq^T)^2)
    {
        dim3 grid(8192 / BN, 8192 / BM);          // (64, 64)
        gemm_h<2048, 8192, true><<<grid, 128, SMEM_TOTAL>>>(xh, wfcq, (void*)h2);
    }

    // 3. out = h2 @ wpjq^T   (fp32 out)
    {
        dim3 grid(2048 / BN, 8192 / BM);          // (16, 64)
        gemm_h<8192, 2048, false><<<grid, 128, SMEM_TOTAL>>>(h2, wpjq, (void*)out);
    }
}

// round 15
// speedup vs baseline: 1.1224x; 1.0000x over previous
#include <cuda_runtime.h>
#include <cuda_fp16.h>
#include <cstdint>
#include <cstddef>

// ---------------------------------------------------------------------------
// out = (relu(x @ qdq(w_fc)^T)^2) @ qdq(w_proj)^T
// M=8192, K1=2048, N1=8192 ; K2=8192, N2=2048
// Round 15: fp16 search REVERTED (R14: argmin in fp16 -> rel_err 9.7e-3).
// Prep = R13-exact fp32 math, restructured into smem-reload passes to cut
// regs 80 -> ~40 (occ 36.6% -> ~70% on a 66%-issue-bound kernel). All fp32
// ops/order identical to R13 -> bit-identical output.
// GEMMs = byte-identical verified R7/R10/R12/R13 mainloop.
// ---------------------------------------------------------------------------

#define BM 128
#define BN 128
#define BKH 64                    // halves per k-tile (128 B rows)
#define STAGE_A (BM * 128)        // bytes
#define STAGE_B (BN * 128)
#define STAGE_BYTES (STAGE_A + STAGE_B)          // 32768
#define SMEM_TOTAL (3 * STAGE_BYTES)             // 98304

// Scratch (allocation-free)
__device__ __align__(256) __half g_xh[8192ull * 2048];
__device__ __align__(256) __half g_wfc[8192ull * 2048];
__device__ __align__(256) __half g_wpj[2048ull * 8192];
__device__ __align__(256) __half g_h2[8192ull * 8192];

// shrink tables (same fp32 literals as verified rounds)
__constant__ float c_shr[16] = {0.4f, 0.44f, 0.48f, 0.52f, 0.56f, 0.6f, 0.64f,
                                0.68f, 0.72f, 0.76f, 0.8f, 0.84f, 0.88f, 0.92f,
                                0.96f, 1.0f};
__constant__ float c_ishr[16] = {2.5f, 1.0f/0.44f, 1.0f/0.48f, 1.0f/0.52f,
                                 1.0f/0.56f, 1.0f/0.6f, 1.0f/0.64f, 1.0f/0.68f,
                                 1.0f/0.72f, 1.0f/0.76f, 1.25f, 1.0f/0.84f,
                                 1.0f/0.88f, 1.0f/0.92f, 1.0f/0.96f, 1.0f};

// ---------------------------------------------------------------------------
__device__ __forceinline__ void cp16(uint32_t s, const void* g) {
    asm volatile("cp.async.cg.shared.global [%0], [%1], 16;" :: "r"(s), "l"(g));
}
__device__ __forceinline__ void cp_commit() { asm volatile("cp.async.commit_group;"); }
template <int N>
__device__ __forceinline__ void cp_wait() { asm volatile("cp.async.wait_group %0;" :: "n"(N)); }

__device__ __forceinline__ void ldsm4(uint32_t& r0, uint32_t& r1, uint32_t& r2,
                                      uint32_t& r3, uint32_t addr) {
    asm volatile("ldmatrix.sync.aligned.m8n8.x4.shared.b16 {%0,%1,%2,%3}, [%4];"
                 : "=r"(r0), "=r"(r1), "=r"(r2), "=r"(r3) : "r"(addr));
}

__device__ __forceinline__ void mma16(float c[4], const uint32_t a[4], const uint32_t b[2]) {
    asm volatile(
        "mma.sync.aligned.m16n8k16.row.col.f32.f16.f16.f32 "
        "{%0,%1,%2,%3}, {%4,%5,%6,%7}, {%8,%9}, {%0,%1,%2,%3};"
        : "+f"(c[0]), "+f"(c[1]), "+f"(c[2]), "+f"(c[3])
        : "r"(a[0]), "r"(a[1]), "r"(a[2]), "r"(a[3]), "r"(b[0]), "r"(b[1]));
}

// ---------------------------------------------------------------------------
// Thread-per-block quant (R13-exact math, smem-reload passes for low regs).
// One warp = 32 consecutive 64-elem blocks staged in padded smem (QPAD=68:
// LDS.128/STS.128 conflict-free). Each lane owns one block.
// ---------------------------------------------------------------------------
#define QPAD 68
__device__ __forceinline__ void quant_warp(const float* __restrict__ w,
                                           __half* __restrict__ wq,
                                           int blk0, int lane,
                                           float* __restrict__ swarp) {
    // ---- stage 32 blocks (2048 floats) coalesced (verified R13) ----
    const float4* src = reinterpret_cast<const float4*>(w + (size_t)blk0 * 64);
    #pragma unroll
    for (int j = 0; j < 16; j++) {
        float4 v = src[j * 32 + lane];
        int blk = 2 * j + (lane >> 4);
        int chunk = lane & 15;
        *reinterpret_cast<float4*>(swarp + blk * QPAD + chunk * 4) = v;
    }
    __syncwarp();

    const float* my = swarp + lane * QPAD;

    // ---- pass 1: amax (max-tree, order-insensitive => exact) ----
    float m0 = 0.f, m1 = 0.f, m2 = 0.f, m3 = 0.f;
    #pragma unroll
    for (int j = 0; j < 16; j++) {
        float4 v = *reinterpret_cast<const float4*>(my + 4 * j);
        m0 = fmaxf(m0, fabsf(v.x)); m1 = fmaxf(m1, fabsf(v.y));
        m2 = fmaxf(m2, fabsf(v.z)); m3 = fmaxf(m3, fabsf(v.w));
    }
    float am = fmaxf(fmaxf(fmaxf(m0, m1), fmaxf(m2, m3)), 1e-8f);
    float base = __fdiv_rn(am, 15.0f);
    float invb = __fdiv_rn(15.0f, am);

    // ---- pass 2: shrink search, fp32-exact (R13 op order), reload from smem
    float best_err = __int_as_float(0x7f800000);
    float bs = base, binv = invb;
    #pragma unroll 2
    for (int i = 0; i < 16; i++) {
        float s = base * c_shr[i];
        float inv = invb * c_ishr[i];
        float a0 = 0.f, a1 = 0.f, a2 = 0.f, a3 = 0.f;
        #pragma unroll
        for (int j = 0; j < 16; j++) {
            float4 v = *reinterpret_cast<const float4*>(my + 4 * j);
            float q, dd;
            q = fminf(fmaxf(rintf(v.x * inv), -15.f), 15.f);
            dd = fmaf(q, s, -v.x); a0 = fmaf(dd, dd, a0);
            q = fminf(fmaxf(rintf(v.y * inv), -15.f), 15.f);
            dd = fmaf(q, s, -v.y); a1 = fmaf(dd, dd, a1);
            q = fminf(fmaxf(rintf(v.z * inv), -15.f), 15.f);
            dd = fmaf(q, s, -v.z); a2 = fmaf(dd, dd, a2);
            q = fminf(fmaxf(rintf(v.w * inv), -15.f), 15.f);
            dd = fmaf(q, s, -v.w); a3 = fmaf(dd, dd, a3);
        }
        float e = (a0 + a1) + (a2 + a3);
        if (e < best_err) { best_err = e; bs = s; binv = inv; }  // strict <, earliest
    }

    // ---- pass 3: exact fp32 dequant with chosen scale, pack fp16 ----
    uint4* dst = reinterpret_cast<uint4*>(wq + (size_t)(blk0 + lane) * 64);
    #pragma unroll
    for (int p = 0; p < 8; p++) {
        float4 v0 = *reinterpret_cast<const float4*>(my + 8 * p);
        float4 v1 = *reinterpret_cast<const float4*>(my + 8 * p + 4);
        float q0 = fminf(fmaxf(rintf(v0.x * binv), -15.f), 15.f) * bs;
        float q1 = fminf(fmaxf(rintf(v0.y * binv), -15.f), 15.f) * bs;
        float q2 = fminf(fmaxf(rintf(v0.z * binv), -15.f), 15.f) * bs;
        float q3 = fminf(fmaxf(rintf(v0.w * binv), -15.f), 15.f) * bs;
        float q4 = fminf(fmaxf(rintf(v1.x * binv), -15.f), 15.f) * bs;
        float q5 = fminf(fmaxf(rintf(v1.y * binv), -15.f), 15.f) * bs;
        float q6 = fminf(fmaxf(rintf(v1.z * binv), -15.f), 15.f) * bs;
        float q7 = fminf(fmaxf(rintf(v1.w * binv), -15.f), 15.f) * bs;
        __half2 h0 = __floats2half2_rn(q0, q1);
        __half2 h1 = __floats2half2_rn(q2, q3);
        __half2 h2 = __floats2half2_rn(q4, q5);
        __half2 h3 = __floats2half2_rn(q6, q7);
        uint4 o;
        o.x = *reinterpret_cast<uint32_t*>(&h0);
        o.y = *reinterpret_cast<uint32_t*>(&h1);
        o.z = *reinterpret_cast<uint32_t*>(&h2);
        o.w = *reinterpret_cast<uint32_t*>(&h3);
        dst[p] = o;
    }
}

// Fused prep: [0,QB) quant wfc, [QB,2QB) quant wproj, rest: x->fp16.
#define QB_CTAS 2048             // 262144 blocks / 128 per CTA
#define CONV_CTAS 4096
__global__ __launch_bounds__(128)
void prep_kernel(const float* __restrict__ wfc, const float* __restrict__ wpj,
                 const float* __restrict__ x,
                 __half* __restrict__ wfcq, __half* __restrict__ wpjq,
                 __half* __restrict__ xh) {
    __shared__ float stage[4][32 * QPAD];
    int cta = blockIdx.x;
    if (cta < 2 * QB_CTAS) {
        const float* w = wfc;
        __half* wq = wfcq;
        int local = cta;
        if (cta >= QB_CTAS) { w = wpj; wq = wpjq; local = cta - QB_CTAS; }
        int warp = threadIdx.x >> 5;
        int lane = threadIdx.x & 31;
        int blk0 = (local * 4 + warp) * 32;
        quant_warp(w, wq, blk0, lane, stage[warp]);
    } else {
        int bid = cta - 2 * QB_CTAS;
        const int n4 = (8192 * 2048) / 4;
        int i = bid * 128 + threadIdx.x;
        const int stride = CONV_CTAS * 128;
        for (; i < n4; i += stride) {
            float4 v = reinterpret_cast<const float4*>(x)[i];
            __half2 h0 = __floats2half2_rn(v.x, v.y);
            __half2 h1 = __floats2half2_rn(v.z, v.w);
            uint2 pk;
            pk.x = *reinterpret_cast<uint32_t*>(&h0);
            pk.y = *reinterpret_cast<uint32_t*>(&h1);
            reinterpret_cast<uint2*>(xh)[i] = pk;
        }
    }
}

// ---------------------------------------------------------------------------
// TN GEMM: C[M,N] = A[M,K] @ B[N,K]^T, fp16 in, fp32 accum.
// 128 threads, 4 warps 2x2, 64x64 warp tile, 3 stages (verified R7-R13).
// ---------------------------------------------------------------------------
template <int K, int NN, bool RELUSQ>
__global__ __launch_bounds__(128, 2)
void gemm_h(const __half* __restrict__ A, const __half* __restrict__ B,
            void* __restrict__ Cv) {
    extern __shared__ char smem[];
    const uint32_t sb = (uint32_t)__cvta_generic_to_shared(smem);

    const int tid = threadIdx.x;
    const int lane = tid & 31;
    const int warp = tid >> 5;
    const int wm = warp >> 1;
    const int wn = warp & 1;
    const int bm = blockIdx.y;
    const int bn = blockIdx.x;

    const int lrow = tid >> 3;
    const int lc = tid & 7;
    const uint32_t lswz = (uint32_t)((lc ^ (lrow & 7)) << 4);
    const __half* aP = A + (size_t)(bm * BM + lrow) * K + lc * 8;
    const __half* bP = B + (size_t)(bn * BN + lrow) * K + lc * 8;
    const uint32_t lsm = lrow * 128 + lswz;

    auto load_stage = [&](uint32_t stg_off, const __half* ag, const __half* bg) {
        uint32_t as = sb + stg_off + lsm;
        uint32_t bs = as + STAGE_A;
        #pragma unroll
        for (int i = 0; i < 8; i++)
            cp16(as + i * (16 * 128), ag + i * (16 * K));
        #pragma unroll
        for (int i = 0; i < 8; i++)
            cp16(bs + i * (16 * 128), bg + i * (16 * K));
        cp_commit();
    };

    const int trow = lane & 7;
    const int tile = lane >> 3;
    const int t01 = tile & 1;
    const int t2 = tile >> 1;
    const uint32_t Aboff = (uint32_t)((wm * 64 + t01 * 8 + trow) * 128);
    const uint32_t Bboff = (uint32_t)(STAGE_A + (wn * 64 + t01 * 8 + trow) * 128);
    uint32_t swz[4];
    #pragma unroll
    for (int kk = 0; kk < 4; kk++)
        swz[kk] = (uint32_t)((((2 * kk + t2) ^ trow)) << 4);

    float c[4][8][4];
    #pragma unroll
    for (int mi = 0; mi < 4; mi++)
        #pragma unroll
        for (int ni = 0; ni < 8; ni++)
            #pragma unroll
            for (int r = 0; r < 4; r++) c[mi][ni][r] = 0.f;

    constexpr int KT = K / BKH;
    static_assert((KT - 2) % 3 == 0, "loop needs KT mod 3 == 2");

    uint32_t fa[2][4][4];
    uint32_t fb[2][8][2];

    auto loadfrag = [&](int buf, uint32_t stgA, uint32_t stgB, uint32_t sz) {
        #pragma unroll
        for (int mi = 0; mi < 4; mi++)
            ldsm4(fa[buf][mi][0], fa[buf][mi][1], fa[buf][mi][2], fa[buf][mi][3],
                  stgA + mi * 2048 + sz);
        #pragma unroll
        for (int nb = 0; nb < 4; nb++) {
            uint32_t r0, r1, r2, r3;
            ldsm4(r0, r1, r2, r3, stgB + nb * 2048 + sz);
            fb[buf][2 * nb][0] = r0; fb[buf][2 * nb][1] = r2;
            fb[buf][2 * nb + 1][0] = r1; fb[buf][2 * nb + 1][1] = r3;
        }
    };
    auto mmablock = [&](int buf) {
        #pragma unroll
        for (int mi = 0; mi < 4; mi++)
            #pragma unroll
            for (int ni = 0; ni < 8; ni++)
                mma16(c[mi][ni], fa[buf][mi], fb[buf][ni]);
    };

    load_stage(0, aP, bP);
    load_stage(STAGE_BYTES, aP + BKH, bP + BKH);
    const __half* apre = aP + 2 * BKH;
    const __half* bpre = bP + 2 * BKH;

    auto step = [&](uint32_t stg_off, uint32_t nxt_off, bool preload, bool last) {
        if (last) cp_wait<0>(); else cp_wait<1>();
        __syncthreads();
        const uint32_t stgA = sb + stg_off + Aboff;
        const uint32_t stgB = sb + stg_off + Bboff;
        loadfrag(0, stgA, stgB, swz[0]);
        if (preload) {
            load_stage(nxt_off, apre, bpre);
            apre += BKH; bpre += BKH;
        }
        loadfrag(1, stgA, stgB, swz[1]);
        mmablock(0);
        loadfrag(0, stgA, stgB, swz[2]);
        mmablock(1);
        loadfrag(1, stgA, stgB, swz[3]);
        mmablock(0);
        mmablock(1);
    };

    constexpr uint32_t S0 = 0, S1 = STAGE_BYTES, S2 = 2 * STAGE_BYTES;
    constexpr int T = (KT - 2) / 3;
    #pragma unroll 1
    for (int t = 0; t < T; t++) {
        step(S0, S2, true, false);
        step(S1, S0, true, false);
        step(S2, S1, true, false);
    }
    step(S0, S2, false, false);
    step(S1, S0, false, true);

    // ---- epilogue ----
    const int g = lane >> 2;
    const int q = lane & 3;
    const int row0 = bm * BM + wm * 64 + g;
    const int col0 = bn * BN + wn * 64 + q * 2;

    if (RELUSQ) {
        __half* C = (__half*)Cv;
        #pragma unroll
        for (int mi = 0; mi < 4; mi++) {
            #pragma unroll
            for (int ni = 0; ni < 8; ni++) {
                float v0 = fmaxf(c[mi][ni][0], 0.f); v0 *= v0;
                float v1 = fmaxf(c[mi][ni][1], 0.f); v1 *= v1;
                float v2 = fmaxf(c[mi][ni][2], 0.f); v2 *= v2;
                float v3 = fmaxf(c[mi][ni][3], 0.f); v3 *= v3;
                int r = row0 + mi * 16;
                int cc = col0 + ni * 8;
                *reinterpret_cast<__half2*>(C + (size_t)r * NN + cc) = __floats2half2_rn(v0, v1);
                *reinterpret_cast<__half2*>(C + (size_t)(r + 8) * NN + cc) = __floats2half2_rn(v2, v3);
            }
        }
    } else {
        float* C = (float*)Cv;
        #pragma unroll
        for (int mi = 0; mi < 4; mi++) {
            #pragma unroll
            for (int ni = 0; ni < 8; ni++) {
                int r = row0 + mi * 16;
                int cc = col0 + ni * 8;
                *reinterpret_cast<float2*>(C + (size_t)r * NN + cc) =
                    make_float2(c[mi][ni][0], c[mi][ni][1]);
                *reinterpret_cast<float2*>(C + (size_t)(r + 8) * NN + cc) =
                    make_float2(c[mi][ni][2], c[mi][ni][3]);
            }
        }
    }
}

// ---------------------------------------------------------------------------

extern "C" void kernel_launch(void* const* d_in, const int* in_sizes, int n_in,
                              void* d_out, int out_size) {
    const float* x     = (const float*)d_in[0];   // [8192, 2048]
    const float* wfc   = (const float*)d_in[1];   // [8192, 2048]
    const float* wproj = (const float*)d_in[2];   // [2048, 8192]
    float* out = (float*)d_out;                    // [8192, 2048]

    __half *xh, *wfcq, *wpjq, *h2;
    cudaGetSymbolAddress((void**)&xh, g_xh);
    cudaGetSymbolAddress((void**)&wfcq, g_wfc);
    cudaGetSymbolAddress((void**)&wpjq, g_wpj);
    cudaGetSymbolAddress((void**)&h2, g_h2);

    void (*g1)(const __half*, const __half*, void*) = gemm_h<2048, 8192, true>;
    void (*g2)(const __half*, const __half*, void*) = gemm_h<8192, 2048, false>;
    cudaFuncSetAttribute(g1, cudaFuncAttributeMaxDynamicSharedMemorySize, SMEM_TOTAL);
    cudaFuncSetAttribute(g2, cudaFuncAttributeMaxDynamicSharedMemorySize, SMEM_TOTAL);

    // 1. fused prep: quant wfc + quant wproj + x->fp16 (one launch)
    prep_kernel<<<2 * QB_CTAS + CONV_CTAS, 128>>>(wfc, wproj, x, wfcq, wpjq, xh);

    // 2. h2 = half(relu(x @ wfcq^T)^2)
    {
        dim3 grid(8192 / BN, 8192 / BM);          // (64, 64)
        gemm_h<2048, 8192, true><<<grid, 128, SMEM_TOTAL>>>(xh, wfcq, (void*)h2);
    }

    // 3. out = h2 @ wpjq^T   (fp32 out)
    {
        dim3 grid(2048 / BN, 8192 / BM);          // (16, 64)
        gemm_h<8192, 2048, false><<<grid, 128, SMEM_TOTAL>>>(h2, wpjq, (void*)out);
    }
}

// round 16
// speedup vs baseline: 1.1253x; 1.0026x over previous
#include <cuda_runtime.h>
#include <cuda_fp16.h>
#include <cstdint>
#include <cstddef>

// ---------------------------------------------------------------------------
// out = (relu(x @ qdq(w_fc)^T)^2) @ qdq(w_proj)^T
// M=8192, K1=2048, N1=8192 ; K2=8192, N2=2048
// Round 16: hide wproj quantization inside GEMM1. GEMM1 grid (64,96): bm<64
// CTAs run the byte-identical verified GEMM mainloop; bm>=64 CTAs (scheduled
// last -> fill GEMM1's tail waves / idle issue slots) run verified R13
// quant_warp on wproj using dynamic smem as staging. wpjq is complete before
// GEMM2 by stream ordering. Prep = quant wfc + x->fp16 only.
// ---------------------------------------------------------------------------

#define BM 128
#define BN 128
#define BKH 64                    // halves per k-tile (128 B rows)
#define STAGE_A (BM * 128)        // bytes
#define STAGE_B (BN * 128)
#define STAGE_BYTES (STAGE_A + STAGE_B)          // 32768
#define SMEM_TOTAL (3 * STAGE_BYTES)             // 98304

// Scratch (allocation-free)
__device__ __align__(256) __half g_xh[8192ull * 2048];
__device__ __align__(256) __half g_wfc[8192ull * 2048];
__device__ __align__(256) __half g_wpj[2048ull * 8192];
__device__ __align__(256) __half g_h2[8192ull * 8192];

// shrink tables (same fp32 literals as verified rounds)
__constant__ float c_shr[16] = {0.4f, 0.44f, 0.48f, 0.52f, 0.56f, 0.6f, 0.64f,
                                0.68f, 0.72f, 0.76f, 0.8f, 0.84f, 0.88f, 0.92f,
                                0.96f, 1.0f};
__constant__ float c_ishr[16] = {2.5f, 1.0f/0.44f, 1.0f/0.48f, 1.0f/0.52f,
                                 1.0f/0.56f, 1.0f/0.6f, 1.0f/0.64f, 1.0f/0.68f,
                                 1.0f/0.72f, 1.0f/0.76f, 1.25f, 1.0f/0.84f,
                                 1.0f/0.88f, 1.0f/0.92f, 1.0f/0.96f, 1.0f};

// ---------------------------------------------------------------------------
__device__ __forceinline__ void cp16(uint32_t s, const void* g) {
    asm volatile("cp.async.cg.shared.global [%0], [%1], 16;" :: "r"(s), "l"(g));
}
__device__ __forceinline__ void cp_commit() { asm volatile("cp.async.commit_group;"); }
template <int N>
__device__ __forceinline__ void cp_wait() { asm volatile("cp.async.wait_group %0;" :: "n"(N)); }

__device__ __forceinline__ void ldsm4(uint32_t& r0, uint32_t& r1, uint32_t& r2,
                                      uint32_t& r3, uint32_t addr) {
    asm volatile("ldmatrix.sync.aligned.m8n8.x4.shared.b16 {%0,%1,%2,%3}, [%4];"
                 : "=r"(r0), "=r"(r1), "=r"(r2), "=r"(r3) : "r"(addr));
}

__device__ __forceinline__ void mma16(float c[4], const uint32_t a[4], const uint32_t b[2]) {
    asm volatile(
        "mma.sync.aligned.m16n8k16.row.col.f32.f16.f16.f32 "
        "{%0,%1,%2,%3}, {%4,%5,%6,%7}, {%8,%9}, {%0,%1,%2,%3};"
        : "+f"(c[0]), "+f"(c[1]), "+f"(c[2]), "+f"(c[3])
        : "r"(a[0]), "r"(a[1]), "r"(a[2]), "r"(a[3]), "r"(b[0]), "r"(b[1]));
}

// ---------------------------------------------------------------------------
// Thread-per-block quant (verified R13/R15 math). One warp = 32 consecutive
// 64-elem blocks staged in padded smem (QPAD=68, conflict-free). Each lane
// then owns one whole block.
// ---------------------------------------------------------------------------
#define QPAD 68
__device__ __forceinline__ void quant_warp(const float* __restrict__ w,
                                           __half* __restrict__ wq,
                                           int blk0, int lane,
                                           float* __restrict__ swarp) {
    const float4* src = reinterpret_cast<const float4*>(w + (size_t)blk0 * 64);
    #pragma unroll
    for (int j = 0; j < 16; j++) {
        float4 v = src[j * 32 + lane];
        int blk = 2 * j + (lane >> 4);
        int chunk = lane & 15;
        *reinterpret_cast<float4*>(swarp + blk * QPAD + chunk * 4) = v;
    }
    __syncwarp();

    const float* my = swarp + lane * QPAD;

    // pass 1: amax (exact max-tree)
    float m0 = 0.f, m1 = 0.f, m2 = 0.f, m3 = 0.f;
    #pragma unroll
    for (int j = 0; j < 16; j++) {
        float4 v = *reinterpret_cast<const float4*>(my + 4 * j);
        m0 = fmaxf(m0, fabsf(v.x)); m1 = fmaxf(m1, fabsf(v.y));
        m2 = fmaxf(m2, fabsf(v.z)); m3 = fmaxf(m3, fabsf(v.w));
    }
    float am = fmaxf(fmaxf(fmaxf(m0, m1), fmaxf(m2, m3)), 1e-8f);
    float base = __fdiv_rn(am, 15.0f);
    float invb = __fdiv_rn(15.0f, am);

    // pass 2: fp32-exact shrink search (verified op order)
    float best_err = __int_as_float(0x7f800000);
    float bs = base, binv = invb;
    #pragma unroll 2
    for (int i = 0; i < 16; i++) {
        float s = base * c_shr[i];
        float inv = invb * c_ishr[i];
        float a0 = 0.f, a1 = 0.f, a2 = 0.f, a3 = 0.f;
        #pragma unroll
        for (int j = 0; j < 16; j++) {
            float4 v = *reinterpret_cast<const float4*>(my + 4 * j);
            float q, dd;
            q = fminf(fmaxf(rintf(v.x * inv), -15.f), 15.f);
            dd = fmaf(q, s, -v.x); a0 = fmaf(dd, dd, a0);
            q = fminf(fmaxf(rintf(v.y * inv), -15.f), 15.f);
            dd = fmaf(q, s, -v.y); a1 = fmaf(dd, dd, a1);
            q = fminf(fmaxf(rintf(v.z * inv), -15.f), 15.f);
            dd = fmaf(q, s, -v.z); a2 = fmaf(dd, dd, a2);
            q = fminf(fmaxf(rintf(v.w * inv), -15.f), 15.f);
            dd = fmaf(q, s, -v.w); a3 = fmaf(dd, dd, a3);
        }
        float e = (a0 + a1) + (a2 + a3);
        if (e < best_err) { best_err = e; bs = s; binv = inv; }
    }

    // pass 3: exact fp32 dequant, pack fp16
    uint4* dst = reinterpret_cast<uint4*>(wq + (size_t)(blk0 + lane) * 64);
    #pragma unroll
    for (int p = 0; p < 8; p++) {
        float4 v0 = *reinterpret_cast<const float4*>(my + 8 * p);
        float4 v1 = *reinterpret_cast<const float4*>(my + 8 * p + 4);
        float q0 = fminf(fmaxf(rintf(v0.x * binv), -15.f), 15.f) * bs;
        float q1 = fminf(fmaxf(rintf(v0.y * binv), -15.f), 15.f) * bs;
        float q2 = fminf(fmaxf(rintf(v0.z * binv), -15.f), 15.f) * bs;
        float q3 = fminf(fmaxf(rintf(v0.w * binv), -15.f), 15.f) * bs;
        float q4 = fminf(fmaxf(rintf(v1.x * binv), -15.f), 15.f) * bs;
        float q5 = fminf(fmaxf(rintf(v1.y * binv), -15.f), 15.f) * bs;
        float q6 = fminf(fmaxf(rintf(v1.z * binv), -15.f), 15.f) * bs;
        float q7 = fminf(fmaxf(rintf(v1.w * binv), -15.f), 15.f) * bs;
        __half2 h0 = __floats2half2_rn(q0, q1);
        __half2 h1 = __floats2half2_rn(q2, q3);
        __half2 h2 = __floats2half2_rn(q4, q5);
        __half2 h3 = __floats2half2_rn(q6, q7);
        uint4 o;
        o.x = *reinterpret_cast<uint32_t*>(&h0);
        o.y = *reinterpret_cast<uint32_t*>(&h1);
        o.z = *reinterpret_cast<uint32_t*>(&h2);
        o.w = *reinterpret_cast<uint32_t*>(&h3);
        dst[p] = o;
    }
}

// Prep: [0,QB) quant wfc, rest: x->fp16. (wproj quant moved into GEMM1.)
#define QB_CTAS 2048             // 262144 blocks / 128 per CTA
#define CONV_CTAS 4096
__global__ __launch_bounds__(128)
void prep_kernel(const float* __restrict__ wfc, const float* __restrict__ x,
                 __half* __restrict__ wfcq, __half* __restrict__ xh) {
    __shared__ float stage[4][32 * QPAD];
    int cta = blockIdx.x;
    if (cta < QB_CTAS) {
        int warp = threadIdx.x >> 5;
        int lane = threadIdx.x & 31;
        int blk0 = (cta * 4 + warp) * 32;
        quant_warp(wfc, wfcq, blk0, lane, stage[warp]);
    } else {
        int bid = cta - QB_CTAS;
        const int n4 = (8192 * 2048) / 4;
        int i = bid * 128 + threadIdx.x;
        const int stride = CONV_CTAS * 128;
        for (; i < n4; i += stride) {
            float4 v = reinterpret_cast<const float4*>(x)[i];
            __half2 h0 = __floats2half2_rn(v.x, v.y);
            __half2 h1 = __floats2half2_rn(v.z, v.w);
            uint2 pk;
            pk.x = *reinterpret_cast<uint32_t*>(&h0);
            pk.y = *reinterpret_cast<uint32_t*>(&h1);
            reinterpret_cast<uint2*>(xh)[i] = pk;
        }
    }
}

// ---------------------------------------------------------------------------
// TN GEMM: C[M,N] = A[M,K] @ B[N,K]^T, fp16 in, fp32 accum.
// 128 threads, 4 warps 2x2, 64x64 warp tile, 3 stages (verified R7-R15).
// FUSEQ: CTAs with blockIdx.y >= M/BM run quant_warp on (qw -> qwq) instead
// (scheduled last -> fill GEMM tail). GEMM-path code untouched.
// ---------------------------------------------------------------------------
template <int K, int NN, bool RELUSQ, bool FUSEQ>
__global__ __launch_bounds__(128, 2)
void gemm_h(const __half* __restrict__ A, const __half* __restrict__ B,
            void* __restrict__ Cv,
            const float* __restrict__ qw, __half* __restrict__ qwq) {
    extern __shared__ char smem[];
    const uint32_t sb = (uint32_t)__cvta_generic_to_shared(smem);

    const int tid = threadIdx.x;
    const int lane = tid & 31;
    const int warp = tid >> 5;
    const int bm = blockIdx.y;
    const int bn = blockIdx.x;

    if (FUSEQ && bm >= 8192 / BM) {
        // quant CTA: index within the appended rows
        int qidx = (bm - 8192 / BM) * gridDim.x + bn;     // 0..2047
        int blk0 = (qidx * 4 + warp) * 32;
        float* swarp = reinterpret_cast<float*>(smem) + warp * (32 * QPAD);
        quant_warp(qw, qwq, blk0, lane, swarp);
        return;
    }

    const int wm = warp >> 1;
    const int wn = warp & 1;

    const int lrow = tid >> 3;
    const int lc = tid & 7;
    const uint32_t lswz = (uint32_t)((lc ^ (lrow & 7)) << 4);
    const __half* aP = A + (size_t)(bm * BM + lrow) * K + lc * 8;
    const __half* bP = B + (size_t)(bn * BN + lrow) * K + lc * 8;
    const uint32_t lsm = lrow * 128 + lswz;

    auto load_stage = [&](uint32_t stg_off, const __half* ag, const __half* bg) {
        uint32_t as = sb + stg_off + lsm;
        uint32_t bs = as + STAGE_A;
        #pragma unroll
        for (int i = 0; i < 8; i++)
            cp16(as + i * (16 * 128), ag + i * (16 * K));
        #pragma unroll
        for (int i = 0; i < 8; i++)
            cp16(bs + i * (16 * 128), bg + i * (16 * K));
        cp_commit();
    };

    const int trow = lane & 7;
    const int tile = lane >> 3;
    const int t01 = tile & 1;
    const int t2 = tile >> 1;
    const uint32_t Aboff = (uint32_t)((wm * 64 + t01 * 8 + trow) * 128);
    const uint32_t Bboff = (uint32_t)(STAGE_A + (wn * 64 + t01 * 8 + trow) * 128);
    uint32_t swz[4];
    #pragma unroll
    for (int kk = 0; kk < 4; kk++)
        swz[kk] = (uint32_t)((((2 * kk + t2) ^ trow)) << 4);

    float c[4][8][4];
    #pragma unroll
    for (int mi = 0; mi < 4; mi++)
        #pragma unroll
        for (int ni = 0; ni < 8; ni++)
            #pragma unroll
            for (int r = 0; r < 4; r++) c[mi][ni][r] = 0.f;

    constexpr int KT = K / BKH;
    static_assert((KT - 2) % 3 == 0, "loop needs KT mod 3 == 2");

    uint32_t fa[2][4][4];
    uint32_t fb[2][8][2];

    auto loadfrag = [&](int buf, uint32_t stgA, uint32_t stgB, uint32_t sz) {
        #pragma unroll
        for (int mi = 0; mi < 4; mi++)
            ldsm4(fa[buf][mi][0], fa[buf][mi][1], fa[buf][mi][2], fa[buf][mi][3],
                  stgA + mi * 2048 + sz);
        #pragma unroll
        for (int nb = 0; nb < 4; nb++) {
            uint32_t r0, r1, r2, r3;
            ldsm4(r0, r1, r2, r3, stgB + nb * 2048 + sz);
            fb[buf][2 * nb][0] = r0; fb[buf][2 * nb][1] = r2;
            fb[buf][2 * nb + 1][0] = r1; fb[buf][2 * nb + 1][1] = r3;
        }
    };
    auto mmablock = [&](int buf) {
        #pragma unroll
        for (int mi = 0; mi < 4; mi++)
            #pragma unroll
            for (int ni = 0; ni < 8; ni++)
                mma16(c[mi][ni], fa[buf][mi], fb[buf][ni]);
    };

    load_stage(0, aP, bP);
    load_stage(STAGE_BYTES, aP + BKH, bP + BKH);
    const __half* apre = aP + 2 * BKH;
    const __half* bpre = bP + 2 * BKH;

    auto step = [&](uint32_t stg_off, uint32_t nxt_off, bool preload, bool last) {
        if (last) cp_wait<0>(); else cp_wait<1>();
        __syncthreads();
        const uint32_t stgA = sb + stg_off + Aboff;
        const uint32_t stgB = sb + stg_off + Bboff;
        loadfrag(0, stgA, stgB, swz[0]);
        if (preload) {
            load_stage(nxt_off, apre, bpre);
            apre += BKH; bpre += BKH;
        }
        loadfrag(1, stgA, stgB, swz[1]);
        mmablock(0);
        loadfrag(0, stgA, stgB, swz[2]);
        mmablock(1);
        loadfrag(1, stgA, stgB, swz[3]);
        mmablock(0);
        mmablock(1);
    };

    constexpr uint32_t S0 = 0, S1 = STAGE_BYTES, S2 = 2 * STAGE_BYTES;
    constexpr int T = (KT - 2) / 3;
    #pragma unroll 1
    for (int t = 0; t < T; t++) {
        step(S0, S2, true, false);
        step(S1, S0, true, false);
        step(S2, S1, true, false);
    }
    step(S0, S2, false, false);
    step(S1, S0, false, true);

    // ---- epilogue ----
    const int g = lane >> 2;
    const int q = lane & 3;
    const int row0 = bm * BM + wm * 64 + g;
    const int col0 = bn * BN + wn * 64 + q * 2;

    if (RELUSQ) {
        __half* C = (__half*)Cv;
        #pragma unroll
        for (int mi = 0; mi < 4; mi++) {
            #pragma unroll
            for (int ni = 0; ni < 8; ni++) {
                float v0 = fmaxf(c[mi][ni][0], 0.f); v0 *= v0;
                float v1 = fmaxf(c[mi][ni][1], 0.f); v1 *= v1;
                float v2 = fmaxf(c[mi][ni][2], 0.f); v2 *= v2;
                float v3 = fmaxf(c[mi][ni][3], 0.f); v3 *= v3;
                int r = row0 + mi * 16;
                int cc = col0 + ni * 8;
                *reinterpret_cast<__half2*>(C + (size_t)r * NN + cc) = __floats2half2_rn(v0, v1);
                *reinterpret_cast<__half2*>(C + (size_t)(r + 8) * NN + cc) = __floats2half2_rn(v2, v3);
            }
        }
    } else {
        float* C = (float*)Cv;
        #pragma unroll
        for (int mi = 0; mi < 4; mi++) {
            #pragma unroll
            for (int ni = 0; ni < 8; ni++) {
                int r = row0 + mi * 16;
                int cc = col0 + ni * 8;
                *reinterpret_cast<float2*>(C + (size_t)r * NN + cc) =
                    make_float2(c[mi][ni][0], c[mi][ni][1]);
                *reinterpret_cast<float2*>(C + (size_t)(r + 8) * NN + cc) =
                    make_float2(c[mi][ni][2], c[mi][ni][3]);
            }
        }
    }
}

// ---------------------------------------------------------------------------

extern "C" void kernel_launch(void* const* d_in, const int* in_sizes, int n_in,
                              void* d_out, int out_size) {
    const float* x     = (const float*)d_in[0];   // [8192, 2048]
    const float* wfc   = (const float*)d_in[1];   // [8192, 2048]
    const float* wproj = (const float*)d_in[2];   // [2048, 8192]
    float* out = (float*)d_out;                    // [8192, 2048]

    __half *xh, *wfcq, *wpjq, *h2;
    cudaGetSymbolAddress((void**)&xh, g_xh);
    cudaGetSymbolAddress((void**)&wfcq, g_wfc);
    cudaGetSymbolAddress((void**)&wpjq, g_wpj);
    cudaGetSymbolAddress((void**)&h2, g_h2);

    void (*g1)(const __half*, const __half*, void*, const float*, __half*) =
        gemm_h<2048, 8192, true, true>;
    void (*g2)(const __half*, const __half*, void*, const float*, __half*) =
        gemm_h<8192, 2048, false, false>;
    cudaFuncSetAttribute(g1, cudaFuncAttributeMaxDynamicSharedMemorySize, SMEM_TOTAL);
    cudaFuncSetAttribute(g2, cudaFuncAttributeMaxDynamicSharedMemorySize, SMEM_TOTAL);

    // 1. prep: quant wfc + x->fp16 (wproj quant is fused into GEMM1)
    prep_kernel<<<QB_CTAS + CONV_CTAS, 128>>>(wfc, x, wfcq, xh);

    // 2. h2 = half(relu(x @ wfcq^T)^2)  + tail CTAs quantize wproj
    {
        dim3 grid(8192 / BN, 8192 / BM + 32);     // (64, 96): rows 64..95 = quant
        gemm_h<2048, 8192, true, true><<<grid, 128, SMEM_TOTAL>>>(
            xh, wfcq, (void*)h2, wproj, wpjq);
    }

    // 3. out = h2 @ wpjq^T   (fp32 out)
    {
        dim3 grid(2048 / BN, 8192 / BM);          // (16, 64)
        gemm_h<8192, 2048, false, false><<<grid, 128, SMEM_TOTAL>>>(
            h2, wpjq, (void*)out, nullptr, nullptr);
    }
}